// round 12
// baseline (speedup 1.0000x reference)
#include <cuda_runtime.h>
#include <cuda_fp16.h>
#include <math.h>
#include <stdint.h>

#define N_NODES 50000
#define N_EDGES 800000
#define F0 128
#define F1 96
#define F2 96
#define F3 40
#define NBLK 74
#define CSR_THREADS 1024
#define CHUNK ((N_NODES + NBLK - 1) / NBLK)   // 676
#define MBLK 148
#define MTHREADS 1024
#define MWARPS (MBLK * (MTHREADS / 32))       // 4736 warps

// ---------------- scratch (static device globals; no allocation) ----------------
__device__ int    g_deg[N_NODES];
__device__ int    g_cur[N_NODES];
__device__ int    g_off[N_NODES + 1];
__device__ int    g_csr[N_EDGES];
__device__ int    g_bsum[NBLK];
__device__ int    g_barrier_ctr;   // csr kernel
__device__ int    g_done_ctr;
__device__ int    g_bar2;          // mega kernel
__device__ int    g_done2;
__device__ int    g_tile2;         // work-stealing counters
__device__ int    g_tile3;
__device__ __half g_t1[(size_t)N_NODES * F1];
__device__ __half g_h1[(size_t)N_NODES * F1];
__device__ __half g_t2[(size_t)N_NODES * F2];
__device__ __half g_h2[(size_t)N_NODES * F2];
__device__ __half g_t3[(size_t)N_NODES * F3];

// ---------------- edge index access ----------------
__device__ __forceinline__ int edge_src(const int* ei, int e, int is64) {
    return is64 ? ei[2 * e] : ei[e];
}
__device__ __forceinline__ int edge_dst(const int* ei, int e, int is64) {
    return is64 ? ei[2 * (N_EDGES + e)] : ei[N_EDGES + e];
}

// ---------------- software grid barriers ----------------
__device__ __forceinline__ void grid_barrier_n(int* ctr, int phase, int nblk) {
    __syncthreads();
    if (threadIdx.x == 0) {
        __threadfence();
        atomicAdd(ctr, 1);
        int target = phase * nblk;
        while ((*(volatile int*)ctr) - target < 0)
            __nanosleep(64);
    }
    __syncthreads();
    __threadfence();
}

// ---------------- single persistent CSR-build kernel ----------------
__global__ void __launch_bounds__(CSR_THREADS) csr_build_kernel(const int* __restrict__ ei) {
    __shared__ int s_is64;
    __shared__ int s_boff;
    __shared__ int wsum[32];

    int tid  = threadIdx.x;
    int lane = tid & 31, w = tid >> 5;
    int gtid = blockIdx.x * CSR_THREADS + tid;
    constexpr int NT = NBLK * CSR_THREADS;

    if (tid < 32) {
        int acc = 0;
#pragma unroll
        for (int j = 0; j < 4; j++) acc |= ei[1 + 2 * (tid * 4 + j)];
#pragma unroll
        for (int o = 16; o > 0; o >>= 1) acc |= __shfl_xor_sync(0xffffffffu, acc, o);
        if (tid == 0) s_is64 = (acc == 0) ? 1 : 0;
    }
    __syncthreads();
    int is64 = s_is64;

    for (int i = gtid; i < N_NODES; i += NT) g_deg[i] = 0;
    grid_barrier_n(&g_barrier_ctr, 1, NBLK);

    for (int e = gtid; e < N_EDGES; e += NT)
        atomicAdd(&g_deg[edge_dst(ei, e, is64)], 1);
    grid_barrier_n(&g_barrier_ctr, 2, NBLK);

    int cbase = blockIdx.x * CHUNK;
    int i0 = cbase + tid;
    int v = (tid < CHUNK && i0 < N_NODES) ? g_deg[i0] : 0;
    {
        int s = v;
#pragma unroll
        for (int o = 16; o > 0; o >>= 1) s += __shfl_xor_sync(0xffffffffu, s, o);
        if (lane == 0) wsum[w] = s;
        __syncthreads();
        if (w == 0) {
            int t = wsum[lane];
#pragma unroll
            for (int o = 16; o > 0; o >>= 1) t += __shfl_xor_sync(0xffffffffu, t, o);
            if (lane == 0) g_bsum[blockIdx.x] = t;
        }
    }
    grid_barrier_n(&g_barrier_ctr, 3, NBLK);

    if (tid == 0) {
        int s = 0;
        for (int b = 0; b < (int)blockIdx.x; b++) s += g_bsum[b];
        s_boff = s;
    }
    __syncthreads();
    {
        int incl = v;
#pragma unroll
        for (int o = 1; o < 32; o <<= 1) {
            int u = __shfl_up_sync(0xffffffffu, incl, o);
            if (lane >= o) incl += u;
        }
        if (lane == 31) wsum[w] = incl;
        __syncthreads();
        if (w == 0) {
            int s = wsum[lane];
#pragma unroll
            for (int o = 1; o < 32; o <<= 1) {
                int u = __shfl_up_sync(0xffffffffu, s, o);
                if (lane >= o) s += u;
            }
            wsum[lane] = s;
        }
        __syncthreads();
        incl += ((w > 0) ? wsum[w - 1] : 0) + s_boff;
        if (tid < CHUNK && i0 < N_NODES) {
            g_off[i0 + 1] = incl;
            g_cur[i0]     = incl - v;
        }
        if (blockIdx.x == 0 && tid == 0) g_off[0] = 0;
    }
    grid_barrier_n(&g_barrier_ctr, 4, NBLK);

    for (int e = gtid; e < N_EDGES; e += NT) {
        int d = edge_dst(ei, e, is64);
        int s = edge_src(ei, e, is64);
        int p = atomicAdd(&g_cur[d], 1);
        g_csr[p] = s;
    }

    __syncthreads();
    if (tid == 0) {
        __threadfence();
        int d = atomicAdd(&g_done_ctr, 1);
        if (d == NBLK - 1) {
            g_barrier_ctr = 0;
            g_done_ctr = 0;
            __threadfence();
        }
    }
}

// ---------------- MMA helpers ----------------
__device__ __forceinline__ uint32_t f2tf32(float f) {
    uint32_t r;
    asm("cvt.rna.tf32.f32 %0, %1;" : "=r"(r) : "f"(f));
    return r;
}

__device__ __forceinline__ void mma8_tf32(float c[4], const uint32_t a[4],
                                          uint32_t b0, uint32_t b1) {
    asm volatile(
        "mma.sync.aligned.m16n8k8.row.col.f32.tf32.tf32.f32 "
        "{%0,%1,%2,%3}, {%4,%5,%6,%7}, {%8,%9}, {%0,%1,%2,%3};"
        : "+f"(c[0]), "+f"(c[1]), "+f"(c[2]), "+f"(c[3])
        : "r"(a[0]), "r"(a[1]), "r"(a[2]), "r"(a[3]), "r"(b0), "r"(b1));
}

__device__ __forceinline__ void mma16_f16(float c[4],
                                          uint32_t a0, uint32_t a1, uint32_t a2, uint32_t a3,
                                          uint32_t b0, uint32_t b1) {
    asm volatile(
        "mma.sync.aligned.m16n8k16.row.col.f32.f16.f16.f32 "
        "{%0,%1,%2,%3}, {%4,%5,%6,%7}, {%8,%9}, {%0,%1,%2,%3};"
        : "+f"(c[0]), "+f"(c[1]), "+f"(c[2]), "+f"(c[3])
        : "r"(a0), "r"(a1), "r"(a2), "r"(a3), "r"(b0), "r"(b1));
}

// ---------------- GEMM1: 3xTF32, fp32 X -> fp16 Y (overlapped with CSR) ----------------
template <int K, int N>
__global__ void __launch_bounds__(192, 2) mma_gemm_kernel(
        const float* __restrict__ X, const float* __restrict__ W,
        __half* __restrict__ Y) {
    constexpr int NT  = N / 8;
    constexpr int PAD = (8 - (N % 32) + 32) % 32;
    constexpr int PS  = N + PAD;
    extern __shared__ uint32_t smem[];
    uint32_t* sHi = smem;
    uint32_t* sLo = smem + K * PS;

    int tid = threadIdx.x;
    for (int i = tid; i < K * N; i += 192) {
        int k = i / N, n = i % N;
        float w = __ldg(W + i);
        uint32_t hi = f2tf32(w);
        sHi[k * PS + n] = hi;
        sLo[k * PS + n] = f2tf32(w - __uint_as_float(hi));
    }
    __syncthreads();

    int warp = tid >> 5, lane = tid & 31;
    int tig = lane & 3, grp = lane >> 2;
    int row0 = blockIdx.x * 192 + warp * 32;
    int r0 = row0 + grp,      r1 = row0 + grp + 8;
    int r2 = row0 + grp + 16, r3 = row0 + grp + 24;
    const float* xr0 = X + (size_t)((r0 < N_NODES) ? r0 : (N_NODES - 1)) * K;
    const float* xr1 = X + (size_t)((r1 < N_NODES) ? r1 : (N_NODES - 1)) * K;
    const float* xr2 = X + (size_t)((r2 < N_NODES) ? r2 : (N_NODES - 1)) * K;
    const float* xr3 = X + (size_t)((r3 < N_NODES) ? r3 : (N_NODES - 1)) * K;

    float c0[NT][4], c1[NT][4];
#pragma unroll
    for (int nt = 0; nt < NT; nt++)
#pragma unroll
        for (int j = 0; j < 4; j++) { c0[nt][j] = 0.f; c1[nt][j] = 0.f; }

#pragma unroll 1
    for (int k0 = 0; k0 < K; k0 += 8) {
        float a0 = __ldg(xr0 + k0 + tig);
        float a1 = __ldg(xr1 + k0 + tig);
        float a2 = __ldg(xr0 + k0 + tig + 4);
        float a3 = __ldg(xr1 + k0 + tig + 4);
        float a4 = __ldg(xr2 + k0 + tig);
        float a5 = __ldg(xr3 + k0 + tig);
        float a6 = __ldg(xr2 + k0 + tig + 4);
        float a7 = __ldg(xr3 + k0 + tig + 4);
        uint32_t ahi0[4] = {f2tf32(a0), f2tf32(a1), f2tf32(a2), f2tf32(a3)};
        uint32_t alo0[4] = {f2tf32(a0 - __uint_as_float(ahi0[0])),
                            f2tf32(a1 - __uint_as_float(ahi0[1])),
                            f2tf32(a2 - __uint_as_float(ahi0[2])),
                            f2tf32(a3 - __uint_as_float(ahi0[3]))};
        uint32_t ahi1[4] = {f2tf32(a4), f2tf32(a5), f2tf32(a6), f2tf32(a7)};
        uint32_t alo1[4] = {f2tf32(a4 - __uint_as_float(ahi1[0])),
                            f2tf32(a5 - __uint_as_float(ahi1[1])),
                            f2tf32(a6 - __uint_as_float(ahi1[2])),
                            f2tf32(a7 - __uint_as_float(ahi1[3]))};
        const uint32_t* rHi0 = sHi + (k0 + tig) * PS + grp;
        const uint32_t* rHi1 = sHi + (k0 + tig + 4) * PS + grp;
        const uint32_t* rLo0 = sLo + (k0 + tig) * PS + grp;
        const uint32_t* rLo1 = sLo + (k0 + tig + 4) * PS + grp;
#pragma unroll
        for (int nt = 0; nt < NT; nt++) {
            uint32_t b0h = rHi0[nt * 8], b1h = rHi1[nt * 8];
            uint32_t b0l = rLo0[nt * 8], b1l = rLo1[nt * 8];
            mma8_tf32(c0[nt], ahi0, b0h, b1h);
            mma8_tf32(c0[nt], alo0, b0h, b1h);
            mma8_tf32(c0[nt], ahi0, b0l, b1l);
            mma8_tf32(c1[nt], ahi1, b0h, b1h);
            mma8_tf32(c1[nt], alo1, b0h, b1h);
            mma8_tf32(c1[nt], ahi1, b0l, b1l);
        }
    }

#pragma unroll
    for (int nt = 0; nt < NT; nt++) {
        int col = nt * 8 + 2 * tig;
        if (r0 < N_NODES)
            *(__half2*)(Y + (size_t)r0 * N + col) = __floats2half2_rn(c0[nt][0], c0[nt][1]);
        if (r1 < N_NODES)
            *(__half2*)(Y + (size_t)r1 * N + col) = __floats2half2_rn(c0[nt][2], c0[nt][3]);
        if (r2 < N_NODES)
            *(__half2*)(Y + (size_t)r2 * N + col) = __floats2half2_rn(c1[nt][0], c1[nt][1]);
        if (r3 < N_NODES)
            *(__half2*)(Y + (size_t)r3 * N + col) = __floats2half2_rn(c1[nt][2], c1[nt][3]);
    }
}

// ---------------- fused post-CSR pipeline (one persistent kernel) ----------------
__device__ __forceinline__ void acc_h4(float4& acc, uint2 v) {
    float2 f0 = __half22float2(*reinterpret_cast<__half2*>(&v.x));
    float2 f1 = __half22float2(*reinterpret_cast<__half2*>(&v.y));
    acc.x += f0.x; acc.y += f0.y; acc.z += f1.x; acc.w += f1.y;
}

// aggregation phase: grid-stride warp-per-node. EPI 0: relu->fp16, EPI 1: log_softmax->fp32
template <int D, int EPI>
__device__ void agg_phase(const __half* __restrict__ xin, const float* __restrict__ sbias,
                          void* __restrict__ xout) {
    constexpr int D4 = D / 4;
    int lane = threadIdx.x & 31;
    int gw0  = blockIdx.x * (MTHREADS / 32) + (threadIdx.x >> 5);
    float4 bb = (lane < D4) ? ((const float4*)sbias)[lane] : make_float4(0.f, 0.f, 0.f, 0.f);

    for (int gw = gw0; gw < N_NODES; gw += MWARPS) {
        float4 acc = make_float4(0.f, 0.f, 0.f, 0.f);
        int beg = g_off[gw], end = g_off[gw + 1];
        int e = beg;
        for (; e + 3 < end; e += 4) {
            int s0 = g_csr[e], s1 = g_csr[e + 1], s2 = g_csr[e + 2], s3 = g_csr[e + 3];
            if (lane < D4) {
                uint2 v0 = __ldg((const uint2*)(xin + (size_t)s0 * D) + lane);
                uint2 v1 = __ldg((const uint2*)(xin + (size_t)s1 * D) + lane);
                uint2 v2 = __ldg((const uint2*)(xin + (size_t)s2 * D) + lane);
                uint2 v3 = __ldg((const uint2*)(xin + (size_t)s3 * D) + lane);
                acc_h4(acc, v0); acc_h4(acc, v1); acc_h4(acc, v2); acc_h4(acc, v3);
            }
        }
        for (; e < end; e++) {
            int s0 = g_csr[e];
            if (lane < D4) {
                uint2 v = __ldg((const uint2*)(xin + (size_t)s0 * D) + lane);
                acc_h4(acc, v);
            }
        }
        acc.x += bb.x; acc.y += bb.y; acc.z += bb.z; acc.w += bb.w;

        if (EPI == 0) {
            if (lane < D4) {
                __half2 o0 = __floats2half2_rn(fmaxf(acc.x, 0.f), fmaxf(acc.y, 0.f));
                __half2 o1 = __floats2half2_rn(fmaxf(acc.z, 0.f), fmaxf(acc.w, 0.f));
                uint2 pack;
                pack.x = *reinterpret_cast<uint32_t*>(&o0);
                pack.y = *reinterpret_cast<uint32_t*>(&o1);
                ((uint2*)((__half*)xout + (size_t)gw * D))[lane] = pack;
            }
        } else {
            float m = (lane < D4)
                    ? fmaxf(fmaxf(acc.x, acc.y), fmaxf(acc.z, acc.w))
                    : -INFINITY;
#pragma unroll
            for (int o = 16; o > 0; o >>= 1) m = fmaxf(m, __shfl_xor_sync(0xffffffffu, m, o));
            float s = (lane < D4)
                    ? (expf(acc.x - m) + expf(acc.y - m)) + (expf(acc.z - m) + expf(acc.w - m))
                    : 0.f;
#pragma unroll
            for (int o = 16; o > 0; o >>= 1) s += __shfl_xor_sync(0xffffffffu, s, o);
            float l = m + logf(s);
            if (lane < D4) {
                acc.x -= l; acc.y -= l; acc.z -= l; acc.w -= l;
                ((float4*)((float*)xout + (size_t)gw * D))[lane] = acc;
            }
        }
    }
}

// GEMM phase (fp16 m16n8k16, W hi/lo in smem). Work-stealing over 16-row x col-chunk units.
// CS = column chunks (2 for N=96 -> 48 cols/unit, 1 for N=40).
template <int K, int N, int CS>
__device__ void gemm_phase(const __half* __restrict__ X,
                           const uint32_t* __restrict__ sHi, const uint32_t* __restrict__ sLo,
                           __half* __restrict__ Y, int* __restrict__ ctr) {
    constexpr int PAD = (8 - (N % 32) + 32) % 32;
    constexpr int PS  = N + PAD;
    constexpr int NC  = N / CS;          // cols per unit
    constexpr int NT  = NC / 8;
    constexpr int NRG = N_NODES / 16;    // 3125 row groups (exact)
    constexpr int NUNIT = NRG * CS;

    int lane = threadIdx.x & 31;
    int tig = lane & 3, grp = lane >> 2;

    for (;;) {
        int u = 0;
        if (lane == 0) u = atomicAdd(ctr, 1);
        u = __shfl_sync(0xffffffffu, u, 0);
        if (u >= NUNIT) break;
        int rg = (CS == 1) ? u : (u / CS);
        int ch = (CS == 1) ? 0 : (u % CS);
        int colbase = ch * NC;
        int r0 = rg * 16 + grp, r1 = r0 + 8;
        const __half* xr0 = X + (size_t)r0 * K;
        const __half* xr1 = X + (size_t)r1 * K;

        float c[NT][4];
#pragma unroll
        for (int nt = 0; nt < NT; nt++)
#pragma unroll
            for (int j = 0; j < 4; j++) c[nt][j] = 0.f;

#pragma unroll
        for (int k0 = 0; k0 < K; k0 += 16) {
            uint32_t a0 = __ldg((const uint32_t*)(xr0 + k0 + 2 * tig));
            uint32_t a1 = __ldg((const uint32_t*)(xr1 + k0 + 2 * tig));
            uint32_t a2 = __ldg((const uint32_t*)(xr0 + k0 + 2 * tig + 8));
            uint32_t a3 = __ldg((const uint32_t*)(xr1 + k0 + 2 * tig + 8));
            int kp0 = (k0 >> 1) + tig;
            int kp1 = kp0 + 4;
            const uint32_t* rHi0 = sHi + kp0 * PS + colbase + grp;
            const uint32_t* rHi1 = sHi + kp1 * PS + colbase + grp;
            const uint32_t* rLo0 = sLo + kp0 * PS + colbase + grp;
            const uint32_t* rLo1 = sLo + kp1 * PS + colbase + grp;
#pragma unroll
            for (int nt = 0; nt < NT; nt++) {
                uint32_t b0h = rHi0[nt * 8], b1h = rHi1[nt * 8];
                uint32_t b0l = rLo0[nt * 8], b1l = rLo1[nt * 8];
                mma16_f16(c[nt], a0, a1, a2, a3, b0h, b1h);
                mma16_f16(c[nt], a0, a1, a2, a3, b0l, b1l);
            }
        }

#pragma unroll
        for (int nt = 0; nt < NT; nt++) {
            int col = colbase + nt * 8 + 2 * tig;
            *(__half2*)(Y + (size_t)r0 * N + col) = __floats2half2_rn(c[nt][0], c[nt][1]);
            *(__half2*)(Y + (size_t)r1 * N + col) = __floats2half2_rn(c[nt][2], c[nt][3]);
        }
    }
}

// smem layout (uint32 words)
#define SW2 (48 * 104)
#define SW3 (48 * 40)
#define SMEM_WORDS (2 * SW2 + 2 * SW3 + F1 + F2 + F3)

__global__ void __launch_bounds__(MTHREADS) fused_layers_kernel(
        const float* __restrict__ b1, const float* __restrict__ W2,
        const float* __restrict__ b2, const float* __restrict__ W3,
        const float* __restrict__ b3, float* __restrict__ out) {
    extern __shared__ uint32_t smem[];
    uint32_t* sW2hi = smem;
    uint32_t* sW2lo = sW2hi + SW2;
    uint32_t* sW3hi = sW2lo + SW2;
    uint32_t* sW3lo = sW3hi + SW3;
    float*    sb    = (float*)(sW3lo + SW3);   // [F1 | F2 | F3]

    int tid = threadIdx.x;

    // stage W2 (hi/lo fp16 pairs), W3, biases
    for (int i = tid; i < (F1 / 2) * F2; i += MTHREADS) {
        int kp = i / F2, n = i % F2;
        float w0 = __ldg(W2 + (2 * kp) * F2 + n);
        float w1 = __ldg(W2 + (2 * kp + 1) * F2 + n);
        __half h0 = __float2half_rn(w0), h1 = __float2half_rn(w1);
        __half l0 = __float2half_rn(w0 - __half2float(h0));
        __half l1 = __float2half_rn(w1 - __half2float(h1));
        __half2 hh = __halves2half2(h0, h1), ll = __halves2half2(l0, l1);
        sW2hi[kp * 104 + n] = *reinterpret_cast<uint32_t*>(&hh);
        sW2lo[kp * 104 + n] = *reinterpret_cast<uint32_t*>(&ll);
    }
    for (int i = tid; i < (F2 / 2) * F3; i += MTHREADS) {
        int kp = i / F3, n = i % F3;
        float w0 = __ldg(W3 + (2 * kp) * F3 + n);
        float w1 = __ldg(W3 + (2 * kp + 1) * F3 + n);
        __half h0 = __float2half_rn(w0), h1 = __float2half_rn(w1);
        __half l0 = __float2half_rn(w0 - __half2float(h0));
        __half l1 = __float2half_rn(w1 - __half2float(h1));
        __half2 hh = __halves2half2(h0, h1), ll = __halves2half2(l0, l1);
        sW3hi[kp * 40 + n] = *reinterpret_cast<uint32_t*>(&hh);
        sW3lo[kp * 40 + n] = *reinterpret_cast<uint32_t*>(&ll);
    }
    if (tid < F1) sb[tid] = b1[tid];
    if (tid < F2) sb[F1 + tid] = b2[tid];
    if (tid < F3) sb[F1 + F2 + tid] = b3[tid];
    __syncthreads();

    // phase A: h1 = relu(agg(t1) + b1)
    agg_phase<F1, 0>(g_t1, sb, g_h1);
    grid_barrier_n(&g_bar2, 1, MBLK);

    // phase B: t2 = h1 @ W2
    gemm_phase<F1, F2, 2>(g_h1, sW2hi, sW2lo, g_t2, &g_tile2);
    grid_barrier_n(&g_bar2, 2, MBLK);

    // phase C: h2 = relu(agg(t2) + b2)
    agg_phase<F2, 0>(g_t2, sb + F1, g_h2);
    grid_barrier_n(&g_bar2, 3, MBLK);

    // phase D: t3 = h2 @ W3
    gemm_phase<F2, F3, 1>(g_h2, sW3hi, sW3lo, g_t3, &g_tile3);
    grid_barrier_n(&g_bar2, 4, MBLK);

    // phase E: out = log_softmax(agg(t3) + b3)
    agg_phase<F3, 1>(g_t3, sb + F1 + F2, out);

    // reset counters for next replay
    __syncthreads();
    if (tid == 0) {
        __threadfence();
        int d = atomicAdd(&g_done2, 1);
        if (d == MBLK - 1) {
            g_bar2 = 0;
            g_done2 = 0;
            g_tile2 = 0;
            g_tile3 = 0;
            __threadfence();
        }
    }
}

// ---------------- launch ----------------
extern "C" void kernel_launch(void* const* d_in, const int* in_sizes, int n_in,
                              void* d_out, int out_size) {
    const float* x  = (const float*)d_in[0];
    const float* W1 = (const float*)d_in[1];
    const float* b1 = (const float*)d_in[2];
    const float* W2 = (const float*)d_in[3];
    const float* b2 = (const float*)d_in[4];
    const float* W3 = (const float*)d_in[5];
    const float* b3 = (const float*)d_in[6];
    const int*   ei = (const int*)d_in[7];
    float* out = (float*)d_out;

    __half* p_t1;
    cudaGetSymbolAddress((void**)&p_t1, g_t1);

    constexpr int PS1 = F1 + ((8 - (F1 % 32) + 32) % 32);   // 104
    const int smem1 = 2 * F0 * PS1 * 4;
    const int smemM = SMEM_WORDS * 4;

    static cudaStream_t sB = nullptr;
    static cudaEvent_t ev_fork = nullptr, ev_join = nullptr;
    if (!sB) {
        cudaStreamCreateWithFlags(&sB, cudaStreamNonBlocking);
        cudaEventCreateWithFlags(&ev_fork, cudaEventDisableTiming);
        cudaEventCreateWithFlags(&ev_join, cudaEventDisableTiming);
        cudaFuncSetAttribute(mma_gemm_kernel<F0, F1>,
                             cudaFuncAttributeMaxDynamicSharedMemorySize, smem1);
        cudaFuncSetAttribute(fused_layers_kernel,
                             cudaFuncAttributeMaxDynamicSharedMemorySize, smemM);
    }

    // fork: persistent CSR build on sB, GEMM1 on main stream
    cudaEventRecord(ev_fork, 0);
    cudaStreamWaitEvent(sB, ev_fork, 0);
    csr_build_kernel<<<NBLK, CSR_THREADS, 0, sB>>>(ei);
    cudaEventRecord(ev_join, sB);

    const int gemm_grid = (N_NODES + 191) / 192;

    // main stream: t1 = x @ W1 (independent of CSR)
    mma_gemm_kernel<F0, F1><<<gemm_grid, 192, smem1>>>(x, W1, p_t1);

    // join: fused pipeline needs CSR + t1
    cudaStreamWaitEvent(0, ev_join, 0);

    fused_layers_kernel<<<MBLK, MTHREADS, smemM>>>(b1, W2, b2, W3, b3, out);
}

// round 13
// speedup vs baseline: 1.4204x; 1.4204x over previous
#include <cuda_runtime.h>
#include <cuda_fp16.h>
#include <math.h>
#include <stdint.h>

#define N_NODES 50000
#define N_EDGES 800000
#define F0 128
#define F1 96
#define F2 96
#define F3 40
#define NBLK 74
#define CSR_THREADS 1024
#define CHUNK ((N_NODES + NBLK - 1) / NBLK)   // 676

// ---------------- scratch (static device globals; no allocation) ----------------
__device__ int    g_deg[N_NODES];
__device__ int    g_cur[N_NODES];
__device__ int    g_off[N_NODES + 1];
__device__ int    g_csr[N_EDGES];
__device__ int    g_bsum[NBLK];
__device__ int    g_barrier_ctr;
__device__ int    g_done_ctr;
__device__ __half g_t1[(size_t)N_NODES * F1];   // x @ W1       (fp16)
__device__ __half g_h1[(size_t)N_NODES * F1];   // relu(agg+b)  (fp16)
__device__ __half g_t2[(size_t)N_NODES * F2];   // h1 @ W2      (fp16)
__device__ __half g_h2[(size_t)N_NODES * F2];   // relu(agg+b)  (fp16)
__device__ __half g_t3[(size_t)N_NODES * F3];   // h2 @ W3      (fp16)

// ---------------- edge index access ----------------
__device__ __forceinline__ int edge_src(const int* ei, int e, int is64) {
    return is64 ? ei[2 * e] : ei[e];
}
__device__ __forceinline__ int edge_dst(const int* ei, int e, int is64) {
    return is64 ? ei[2 * (N_EDGES + e)] : ei[N_EDGES + e];
}

// ---------------- software grid barrier (74 co-resident blocks) ----------------
__device__ __forceinline__ void grid_barrier(int phase) {
    __syncthreads();
    if (threadIdx.x == 0) {
        __threadfence();
        atomicAdd(&g_barrier_ctr, 1);
        int target = phase * NBLK;
        while ((*(volatile int*)&g_barrier_ctr) - target < 0)
            __nanosleep(64);
    }
    __syncthreads();
    __threadfence();
}

// ---------------- single persistent CSR-build kernel ----------------
__global__ void __launch_bounds__(CSR_THREADS) csr_build_kernel(const int* __restrict__ ei) {
    __shared__ int s_is64;
    __shared__ int s_boff;
    __shared__ int wsum[32];

    int tid  = threadIdx.x;
    int lane = tid & 31, w = tid >> 5;
    int gtid = blockIdx.x * CSR_THREADS + tid;
    constexpr int NT = NBLK * CSR_THREADS;

    if (tid < 32) {
        int acc = 0;
#pragma unroll
        for (int j = 0; j < 4; j++) acc |= ei[1 + 2 * (tid * 4 + j)];
#pragma unroll
        for (int o = 16; o > 0; o >>= 1) acc |= __shfl_xor_sync(0xffffffffu, acc, o);
        if (tid == 0) s_is64 = (acc == 0) ? 1 : 0;
    }
    __syncthreads();
    int is64 = s_is64;

    for (int i = gtid; i < N_NODES; i += NT) g_deg[i] = 0;
    grid_barrier(1);

    for (int e = gtid; e < N_EDGES; e += NT)
        atomicAdd(&g_deg[edge_dst(ei, e, is64)], 1);
    grid_barrier(2);

    int cbase = blockIdx.x * CHUNK;
    int i0 = cbase + tid;
    int v = (tid < CHUNK && i0 < N_NODES) ? g_deg[i0] : 0;
    {
        int s = v;
#pragma unroll
        for (int o = 16; o > 0; o >>= 1) s += __shfl_xor_sync(0xffffffffu, s, o);
        if (lane == 0) wsum[w] = s;
        __syncthreads();
        if (w == 0) {
            int t = wsum[lane];
#pragma unroll
            for (int o = 16; o > 0; o >>= 1) t += __shfl_xor_sync(0xffffffffu, t, o);
            if (lane == 0) g_bsum[blockIdx.x] = t;
        }
    }
    grid_barrier(3);

    if (tid == 0) {
        int s = 0;
        for (int b = 0; b < (int)blockIdx.x; b++) s += g_bsum[b];
        s_boff = s;
    }
    __syncthreads();
    {
        int incl = v;
#pragma unroll
        for (int o = 1; o < 32; o <<= 1) {
            int u = __shfl_up_sync(0xffffffffu, incl, o);
            if (lane >= o) incl += u;
        }
        if (lane == 31) wsum[w] = incl;
        __syncthreads();
        if (w == 0) {
            int s = wsum[lane];
#pragma unroll
            for (int o = 1; o < 32; o <<= 1) {
                int u = __shfl_up_sync(0xffffffffu, s, o);
                if (lane >= o) s += u;
            }
            wsum[lane] = s;
        }
        __syncthreads();
        incl += ((w > 0) ? wsum[w - 1] : 0) + s_boff;
        if (tid < CHUNK && i0 < N_NODES) {
            g_off[i0 + 1] = incl;
            g_cur[i0]     = incl - v;
        }
        if (blockIdx.x == 0 && tid == 0) g_off[0] = 0;
    }
    grid_barrier(4);

    for (int e = gtid; e < N_EDGES; e += NT) {
        int d = edge_dst(ei, e, is64);
        int s = edge_src(ei, e, is64);
        int p = atomicAdd(&g_cur[d], 1);
        g_csr[p] = s;
    }

    __syncthreads();
    if (tid == 0) {
        __threadfence();
        int d = atomicAdd(&g_done_ctr, 1);
        if (d == NBLK - 1) {
            g_barrier_ctr = 0;
            g_done_ctr = 0;
            __threadfence();
        }
    }
}

// ---------------- MMA helper ----------------
__device__ __forceinline__ void mma16_f16(float c[4],
                                          uint32_t a0, uint32_t a1, uint32_t a2, uint32_t a3,
                                          uint32_t b0, uint32_t b1) {
    asm volatile(
        "mma.sync.aligned.m16n8k16.row.col.f32.f16.f16.f32 "
        "{%0,%1,%2,%3}, {%4,%5,%6,%7}, {%8,%9}, {%0,%1,%2,%3};"
        : "+f"(c[0]), "+f"(c[1]), "+f"(c[2]), "+f"(c[3])
        : "r"(a0), "r"(a1), "r"(a2), "r"(a3), "r"(b0), "r"(b1));
}

// split fp32 pair -> hi/lo half2
__device__ __forceinline__ void split_h2(float2 f, uint32_t& hi, uint32_t& lo) {
    __half2 h = __floats2half2_rn(f.x, f.y);
    float l0 = f.x - __low2float(h);
    float l1 = f.y - __high2float(h);
    __half2 l = __floats2half2_rn(l0, l1);
    hi = *reinterpret_cast<uint32_t*>(&h);
    lo = *reinterpret_cast<uint32_t*>(&l);
}

// ---------------- GEMM1: fp16 MMA, A=x (fp32->hi/lo), B=W1 (hi/lo), 3 passes ----------------
// 192 threads, 32 rows/warp, 192 rows/block.
template <int K, int N>
__global__ void __launch_bounds__(192, 2) mma_gemm_h1_kernel(
        const float* __restrict__ X, const float* __restrict__ W,
        __half* __restrict__ Y) {
    constexpr int NT  = N / 8;
    constexpr int KP  = K / 2;
    constexpr int PAD = (8 - (N % 32) + 32) % 32;
    constexpr int PS  = N + PAD;
    extern __shared__ uint32_t smem[];
    uint32_t* sHi = smem;
    uint32_t* sLo = smem + KP * PS;

    int tid = threadIdx.x;
    for (int i = tid; i < KP * N; i += 192) {
        int kp = i / N, n = i % N;
        float2 wp = make_float2(__ldg(W + (2 * kp) * N + n), __ldg(W + (2 * kp + 1) * N + n));
        uint32_t hi, lo;
        split_h2(wp, hi, lo);
        sHi[kp * PS + n] = hi;
        sLo[kp * PS + n] = lo;
    }
    __syncthreads();

    int warp = tid >> 5, lane = tid & 31;
    int tig = lane & 3, grp = lane >> 2;
    int row0 = blockIdx.x * 192 + warp * 32;
    int r0 = row0 + grp,      r1 = row0 + grp + 8;
    int r2 = row0 + grp + 16, r3 = row0 + grp + 24;
    const float* xr0 = X + (size_t)((r0 < N_NODES) ? r0 : (N_NODES - 1)) * K;
    const float* xr1 = X + (size_t)((r1 < N_NODES) ? r1 : (N_NODES - 1)) * K;
    const float* xr2 = X + (size_t)((r2 < N_NODES) ? r2 : (N_NODES - 1)) * K;
    const float* xr3 = X + (size_t)((r3 < N_NODES) ? r3 : (N_NODES - 1)) * K;

    float c0[NT][4], c1[NT][4];
#pragma unroll
    for (int nt = 0; nt < NT; nt++)
#pragma unroll
        for (int j = 0; j < 4; j++) { c0[nt][j] = 0.f; c1[nt][j] = 0.f; }

#pragma unroll 1
    for (int k0 = 0; k0 < K; k0 += 16) {
        float2 f00 = *(const float2*)(xr0 + k0 + 2 * tig);
        float2 f01 = *(const float2*)(xr1 + k0 + 2 * tig);
        float2 f02 = *(const float2*)(xr0 + k0 + 2 * tig + 8);
        float2 f03 = *(const float2*)(xr1 + k0 + 2 * tig + 8);
        float2 f10 = *(const float2*)(xr2 + k0 + 2 * tig);
        float2 f11 = *(const float2*)(xr3 + k0 + 2 * tig);
        float2 f12 = *(const float2*)(xr2 + k0 + 2 * tig + 8);
        float2 f13 = *(const float2*)(xr3 + k0 + 2 * tig + 8);
        uint32_t ah0[4], al0[4], ah1[4], al1[4];
        split_h2(f00, ah0[0], al0[0]); split_h2(f01, ah0[1], al0[1]);
        split_h2(f02, ah0[2], al0[2]); split_h2(f03, ah0[3], al0[3]);
        split_h2(f10, ah1[0], al1[0]); split_h2(f11, ah1[1], al1[1]);
        split_h2(f12, ah1[2], al1[2]); split_h2(f13, ah1[3], al1[3]);

        int kp0 = (k0 >> 1) + tig;
        int kp1 = kp0 + 4;
        const uint32_t* rHi0 = sHi + kp0 * PS + grp;
        const uint32_t* rHi1 = sHi + kp1 * PS + grp;
        const uint32_t* rLo0 = sLo + kp0 * PS + grp;
        const uint32_t* rLo1 = sLo + kp1 * PS + grp;
#pragma unroll
        for (int nt = 0; nt < NT; nt++) {
            uint32_t b0h = rHi0[nt * 8], b1h = rHi1[nt * 8];
            uint32_t b0l = rLo0[nt * 8], b1l = rLo1[nt * 8];
            mma16_f16(c0[nt], ah0[0], ah0[1], ah0[2], ah0[3], b0h, b1h);  // hi*hi
            mma16_f16(c0[nt], al0[0], al0[1], al0[2], al0[3], b0h, b1h);  // lo*hi
            mma16_f16(c0[nt], ah0[0], ah0[1], ah0[2], ah0[3], b0l, b1l);  // hi*lo
            mma16_f16(c1[nt], ah1[0], ah1[1], ah1[2], ah1[3], b0h, b1h);
            mma16_f16(c1[nt], al1[0], al1[1], al1[2], al1[3], b0h, b1h);
            mma16_f16(c1[nt], ah1[0], ah1[1], ah1[2], ah1[3], b0l, b1l);
        }
    }

#pragma unroll
    for (int nt = 0; nt < NT; nt++) {
        int col = nt * 8 + 2 * tig;
        if (r0 < N_NODES)
            *(__half2*)(Y + (size_t)r0 * N + col) = __floats2half2_rn(c0[nt][0], c0[nt][1]);
        if (r1 < N_NODES)
            *(__half2*)(Y + (size_t)r1 * N + col) = __floats2half2_rn(c0[nt][2], c0[nt][3]);
        if (r2 < N_NODES)
            *(__half2*)(Y + (size_t)r2 * N + col) = __floats2half2_rn(c1[nt][0], c1[nt][1]);
        if (r3 < N_NODES)
            *(__half2*)(Y + (size_t)r3 * N + col) = __floats2half2_rn(c1[nt][2], c1[nt][3]);
    }
}

// ---------------- GEMM2/3: fp16 m16n8k16, A fp16 direct, W = hi+lo (2 passes) ----------------
template <int K, int N>
__global__ void __launch_bounds__(192, 2) mma_gemm_h_kernel(
        const __half* __restrict__ X, const float* __restrict__ W,
        __half* __restrict__ Y) {
    constexpr int NT  = N / 8;
    constexpr int KP  = K / 2;
    constexpr int PAD = (8 - (N % 32) + 32) % 32;
    constexpr int PS  = N + PAD;
    extern __shared__ uint32_t smem[];
    uint32_t* sHi = smem;
    uint32_t* sLo = smem + KP * PS;

    int tid = threadIdx.x;
    for (int i = tid; i < KP * N; i += 192) {
        int kp = i / N, n = i % N;
        float2 wp = make_float2(__ldg(W + (2 * kp) * N + n), __ldg(W + (2 * kp + 1) * N + n));
        uint32_t hi, lo;
        split_h2(wp, hi, lo);
        sHi[kp * PS + n] = hi;
        sLo[kp * PS + n] = lo;
    }
    __syncthreads();

    int warp = tid >> 5, lane = tid & 31;
    int tig = lane & 3, grp = lane >> 2;
    int row0 = blockIdx.x * 192 + warp * 32;
    int r0 = row0 + grp,      r1 = row0 + grp + 8;
    int r2 = row0 + grp + 16, r3 = row0 + grp + 24;
    const __half* xr0 = X + (size_t)((r0 < N_NODES) ? r0 : (N_NODES - 1)) * K;
    const __half* xr1 = X + (size_t)((r1 < N_NODES) ? r1 : (N_NODES - 1)) * K;
    const __half* xr2 = X + (size_t)((r2 < N_NODES) ? r2 : (N_NODES - 1)) * K;
    const __half* xr3 = X + (size_t)((r3 < N_NODES) ? r3 : (N_NODES - 1)) * K;

    float c0[NT][4], c1[NT][4];
#pragma unroll
    for (int nt = 0; nt < NT; nt++)
#pragma unroll
        for (int j = 0; j < 4; j++) { c0[nt][j] = 0.f; c1[nt][j] = 0.f; }

#pragma unroll 1
    for (int k0 = 0; k0 < K; k0 += 16) {
        uint32_t a00 = __ldg((const uint32_t*)(xr0 + k0 + 2 * tig));
        uint32_t a01 = __ldg((const uint32_t*)(xr1 + k0 + 2 * tig));
        uint32_t a02 = __ldg((const uint32_t*)(xr0 + k0 + 2 * tig + 8));
        uint32_t a03 = __ldg((const uint32_t*)(xr1 + k0 + 2 * tig + 8));
        uint32_t a10 = __ldg((const uint32_t*)(xr2 + k0 + 2 * tig));
        uint32_t a11 = __ldg((const uint32_t*)(xr3 + k0 + 2 * tig));
        uint32_t a12 = __ldg((const uint32_t*)(xr2 + k0 + 2 * tig + 8));
        uint32_t a13 = __ldg((const uint32_t*)(xr3 + k0 + 2 * tig + 8));

        int kp0 = (k0 >> 1) + tig;
        int kp1 = kp0 + 4;
        const uint32_t* rHi0 = sHi + kp0 * PS + grp;
        const uint32_t* rHi1 = sHi + kp1 * PS + grp;
        const uint32_t* rLo0 = sLo + kp0 * PS + grp;
        const uint32_t* rLo1 = sLo + kp1 * PS + grp;
#pragma unroll
        for (int nt = 0; nt < NT; nt++) {
            uint32_t b0h = rHi0[nt * 8], b1h = rHi1[nt * 8];
            uint32_t b0l = rLo0[nt * 8], b1l = rLo1[nt * 8];
            mma16_f16(c0[nt], a00, a01, a02, a03, b0h, b1h);
            mma16_f16(c0[nt], a00, a01, a02, a03, b0l, b1l);
            mma16_f16(c1[nt], a10, a11, a12, a13, b0h, b1h);
            mma16_f16(c1[nt], a10, a11, a12, a13, b0l, b1l);
        }
    }

#pragma unroll
    for (int nt = 0; nt < NT; nt++) {
        int col = nt * 8 + 2 * tig;
        if (r0 < N_NODES)
            *(__half2*)(Y + (size_t)r0 * N + col) = __floats2half2_rn(c0[nt][0], c0[nt][1]);
        if (r1 < N_NODES)
            *(__half2*)(Y + (size_t)r1 * N + col) = __floats2half2_rn(c0[nt][2], c0[nt][3]);
        if (r2 < N_NODES)
            *(__half2*)(Y + (size_t)r2 * N + col) = __floats2half2_rn(c1[nt][0], c1[nt][1]);
        if (r3 < N_NODES)
            *(__half2*)(Y + (size_t)r3 * N + col) = __floats2half2_rn(c1[nt][2], c1[nt][3]);
    }
}

// ---------------- gather aggregation (fp16 in, fp32 accum) + fused epilogue ----------------
__device__ __forceinline__ void acc_h4(float4& acc, uint2 v) {
    float2 f0 = __half22float2(*reinterpret_cast<__half2*>(&v.x));
    float2 f1 = __half22float2(*reinterpret_cast<__half2*>(&v.y));
    acc.x += f0.x; acc.y += f0.y; acc.z += f1.x; acc.w += f1.y;
}

// EPI 0: relu(acc+bias) -> fp16   EPI 1: log_softmax(acc+bias) -> fp32
template <int D, int EPI>
__global__ void agg_kernel(const __half* __restrict__ xin, const float* __restrict__ bias,
                           void* __restrict__ xout) {
    int gw   = (blockIdx.x * blockDim.x + threadIdx.x) >> 5;
    int lane = threadIdx.x & 31;
    if (gw >= N_NODES) return;
    constexpr int D4 = D / 4;
    float4 acc = make_float4(0.f, 0.f, 0.f, 0.f);
    int beg = g_off[gw], end = g_off[gw + 1];
    int e = beg;
    for (; e + 3 < end; e += 4) {
        int s0 = g_csr[e], s1 = g_csr[e + 1], s2 = g_csr[e + 2], s3 = g_csr[e + 3];
        if (lane < D4) {
            uint2 v0 = __ldg((const uint2*)(xin + (size_t)s0 * D) + lane);
            uint2 v1 = __ldg((const uint2*)(xin + (size_t)s1 * D) + lane);
            uint2 v2 = __ldg((const uint2*)(xin + (size_t)s2 * D) + lane);
            uint2 v3 = __ldg((const uint2*)(xin + (size_t)s3 * D) + lane);
            acc_h4(acc, v0);
            acc_h4(acc, v1);
            acc_h4(acc, v2);
            acc_h4(acc, v3);
        }
    }
    for (; e < end; e++) {
        int s0 = g_csr[e];
        if (lane < D4) {
            uint2 v = __ldg((const uint2*)(xin + (size_t)s0 * D) + lane);
            acc_h4(acc, v);
        }
    }
    float4 bb = (lane < D4) ? ((const float4*)bias)[lane] : make_float4(0.f, 0.f, 0.f, 0.f);
    acc.x += bb.x; acc.y += bb.y; acc.z += bb.z; acc.w += bb.w;

    if (EPI == 0) {
        if (lane < D4) {
            __half2 o0 = __floats2half2_rn(fmaxf(acc.x, 0.f), fmaxf(acc.y, 0.f));
            __half2 o1 = __floats2half2_rn(fmaxf(acc.z, 0.f), fmaxf(acc.w, 0.f));
            uint2 pack;
            pack.x = *reinterpret_cast<uint32_t*>(&o0);
            pack.y = *reinterpret_cast<uint32_t*>(&o1);
            ((uint2*)((__half*)xout + (size_t)gw * D))[lane] = pack;
        }
    } else {
        float m = (lane < D4)
                ? fmaxf(fmaxf(acc.x, acc.y), fmaxf(acc.z, acc.w))
                : -INFINITY;
#pragma unroll
        for (int o = 16; o > 0; o >>= 1) m = fmaxf(m, __shfl_xor_sync(0xffffffffu, m, o));
        float s = (lane < D4)
                ? (expf(acc.x - m) + expf(acc.y - m)) + (expf(acc.z - m) + expf(acc.w - m))
                : 0.f;
#pragma unroll
        for (int o = 16; o > 0; o >>= 1) s += __shfl_xor_sync(0xffffffffu, s, o);
        float l = m + logf(s);
        if (lane < D4) {
            acc.x -= l; acc.y -= l; acc.z -= l; acc.w -= l;
            ((float4*)((float*)xout + (size_t)gw * D))[lane] = acc;
        }
    }
}

// ---------------- launch ----------------
extern "C" void kernel_launch(void* const* d_in, const int* in_sizes, int n_in,
                              void* d_out, int out_size) {
    const float* x  = (const float*)d_in[0];
    const float* W1 = (const float*)d_in[1];
    const float* b1 = (const float*)d_in[2];
    const float* W2 = (const float*)d_in[3];
    const float* b2 = (const float*)d_in[4];
    const float* W3 = (const float*)d_in[5];
    const float* b3 = (const float*)d_in[6];
    const int*   ei = (const int*)d_in[7];
    float* out = (float*)d_out;

    __half *p_t1, *p_h1, *p_t2, *p_h2, *p_t3;
    cudaGetSymbolAddress((void**)&p_t1, g_t1);
    cudaGetSymbolAddress((void**)&p_h1, g_h1);
    cudaGetSymbolAddress((void**)&p_t2, g_t2);
    cudaGetSymbolAddress((void**)&p_h2, g_h2);
    cudaGetSymbolAddress((void**)&p_t3, g_t3);

    constexpr int PS1 = F1 + ((8 - (F1 % 32) + 32) % 32);   // 104
    constexpr int PS2 = F2 + ((8 - (F2 % 32) + 32) % 32);   // 104
    constexpr int PS3 = F3 + ((8 - (F3 % 32) + 32) % 32);   // 40
    const int smem1 = 2 * (F0 / 2) * PS1 * 4;      // fp16 pairs hi+lo
    const int smem2 = 2 * (F1 / 2) * PS2 * 4;
    const int smem3 = 2 * (F2 / 2) * PS3 * 4;

    static cudaStream_t sB = nullptr;
    static cudaEvent_t ev_fork = nullptr, ev_join = nullptr;
    if (!sB) {
        cudaStreamCreateWithFlags(&sB, cudaStreamNonBlocking);
        cudaEventCreateWithFlags(&ev_fork, cudaEventDisableTiming);
        cudaEventCreateWithFlags(&ev_join, cudaEventDisableTiming);
        cudaFuncSetAttribute(mma_gemm_h1_kernel<F0, F1>,
                             cudaFuncAttributeMaxDynamicSharedMemorySize, smem1);
        cudaFuncSetAttribute(mma_gemm_h_kernel<F1, F2>,
                             cudaFuncAttributeMaxDynamicSharedMemorySize, smem2);
        cudaFuncSetAttribute(mma_gemm_h_kernel<F2, F3>,
                             cudaFuncAttributeMaxDynamicSharedMemorySize, smem3);
    }

    // fork: persistent CSR build on sB, GEMM1 on main stream
    cudaEventRecord(ev_fork, 0);
    cudaStreamWaitEvent(sB, ev_fork, 0);
    csr_build_kernel<<<NBLK, CSR_THREADS, 0, sB>>>(ei);
    cudaEventRecord(ev_join, sB);

    const int agg_grid  = (N_NODES * 32 + 255) / 256;
    const int gemm_grid = (N_NODES + 191) / 192;

    // main stream: t1 = x @ W1 (fp16 MMA, hi/lo both sides)
    mma_gemm_h1_kernel<F0, F1><<<gemm_grid, 192, smem1>>>(x, W1, p_t1);

    // join: aggregation needs CSR
    cudaStreamWaitEvent(0, ev_join, 0);

    // layer 1: h1 = relu(agg(t1) + b1)
    agg_kernel<F1, 0><<<agg_grid, 256>>>(p_t1, b1, p_h1);
    // layer 2
    mma_gemm_h_kernel<F1, F2><<<gemm_grid, 192, smem2>>>(p_h1, W2, p_t2);
    agg_kernel<F2, 0><<<agg_grid, 256>>>(p_t2, b2, p_h2);
    // layer 3 + log_softmax
    mma_gemm_h_kernel<F2, F3><<<gemm_grid, 192, smem3>>>(p_h2, W3, p_t3);
    agg_kernel<F3, 1><<<agg_grid, 256>>>(p_t3, b3, out);
}

// round 14
// speedup vs baseline: 1.4650x; 1.0314x over previous
#include <cuda_runtime.h>
#include <cuda_fp16.h>
#include <math.h>
#include <stdint.h>

#define N_NODES 50000
#define N_EDGES 800000
#define F0 128
#define F1 96
#define F2 96
#define F3 40
#define NBLK 74
#define CSR_THREADS 1024
#define CHUNK ((N_NODES + NBLK - 1) / NBLK)   // 676

// ---------------- scratch (static device globals; no allocation) ----------------
__device__ int    g_deg[N_NODES];
__device__ int    g_cur[N_NODES];
__device__ int    g_off[N_NODES + 1];
__device__ int    g_csr[N_EDGES];
__device__ int    g_bsum[NBLK];
__device__ int    g_barrier_ctr;
__device__ int    g_done_ctr;
__device__ __half g_t1[(size_t)N_NODES * F1];
__device__ __half g_h1[(size_t)N_NODES * F1];
__device__ __half g_t2[(size_t)N_NODES * F2];
__device__ __half g_h2[(size_t)N_NODES * F2];
__device__ __half g_t3[(size_t)N_NODES * F3];

// ---------------- PDL intrinsics ----------------
__device__ __forceinline__ void gdc_launch() {
    asm volatile("griddepcontrol.launch_dependents;");
}
__device__ __forceinline__ void gdc_wait() {
    asm volatile("griddepcontrol.wait;" ::: "memory");
}

// ---------------- edge index access ----------------
__device__ __forceinline__ int edge_src(const int* ei, int e, int is64) {
    return is64 ? ei[2 * e] : ei[e];
}
__device__ __forceinline__ int edge_dst(const int* ei, int e, int is64) {
    return is64 ? ei[2 * (N_EDGES + e)] : ei[N_EDGES + e];
}

// ---------------- software grid barrier (74 co-resident blocks) ----------------
__device__ __forceinline__ void grid_barrier(int phase) {
    __syncthreads();
    if (threadIdx.x == 0) {
        __threadfence();
        atomicAdd(&g_barrier_ctr, 1);
        int target = phase * NBLK;
        while ((*(volatile int*)&g_barrier_ctr) - target < 0)
            __nanosleep(64);
    }
    __syncthreads();
    __threadfence();
}

// ---------------- single persistent CSR-build kernel (MLP-4 edge loops) ----------------
__global__ void __launch_bounds__(CSR_THREADS) csr_build_kernel(const int* __restrict__ ei) {
    __shared__ int s_is64;
    __shared__ int s_boff;
    __shared__ int wsum[32];

    int tid  = threadIdx.x;
    int lane = tid & 31, w = tid >> 5;
    int gtid = blockIdx.x * CSR_THREADS + tid;
    constexpr int NT = NBLK * CSR_THREADS;

    if (tid < 32) {
        int acc = 0;
#pragma unroll
        for (int j = 0; j < 4; j++) acc |= ei[1 + 2 * (tid * 4 + j)];
#pragma unroll
        for (int o = 16; o > 0; o >>= 1) acc |= __shfl_xor_sync(0xffffffffu, acc, o);
        if (tid == 0) s_is64 = (acc == 0) ? 1 : 0;
    }
    __syncthreads();
    int is64 = s_is64;

    // P0: zero degrees
    for (int i = gtid; i < N_NODES; i += NT) g_deg[i] = 0;
    grid_barrier(1);

    // P1: histogram of dst — 4 independent edges per iteration (MLP=4)
    {
        int e = gtid;
        for (; e + 3 * NT < N_EDGES; e += 4 * NT) {
            int d0 = edge_dst(ei, e,          is64);
            int d1 = edge_dst(ei, e + NT,     is64);
            int d2 = edge_dst(ei, e + 2 * NT, is64);
            int d3 = edge_dst(ei, e + 3 * NT, is64);
            atomicAdd(&g_deg[d0], 1);
            atomicAdd(&g_deg[d1], 1);
            atomicAdd(&g_deg[d2], 1);
            atomicAdd(&g_deg[d3], 1);
        }
        for (; e < N_EDGES; e += NT)
            atomicAdd(&g_deg[edge_dst(ei, e, is64)], 1);
    }
    grid_barrier(2);

    // P2: per-block chunk sum
    int cbase = blockIdx.x * CHUNK;
    int i0 = cbase + tid;
    int v = (tid < CHUNK && i0 < N_NODES) ? g_deg[i0] : 0;
    {
        int s = v;
#pragma unroll
        for (int o = 16; o > 0; o >>= 1) s += __shfl_xor_sync(0xffffffffu, s, o);
        if (lane == 0) wsum[w] = s;
        __syncthreads();
        if (w == 0) {
            int t = wsum[lane];
#pragma unroll
            for (int o = 16; o > 0; o >>= 1) t += __shfl_xor_sync(0xffffffffu, t, o);
            if (lane == 0) g_bsum[blockIdx.x] = t;
        }
    }
    grid_barrier(3);

    // P3: scan
    if (tid == 0) {
        int s = 0;
        for (int b = 0; b < (int)blockIdx.x; b++) s += g_bsum[b];
        s_boff = s;
    }
    __syncthreads();
    {
        int incl = v;
#pragma unroll
        for (int o = 1; o < 32; o <<= 1) {
            int u = __shfl_up_sync(0xffffffffu, incl, o);
            if (lane >= o) incl += u;
        }
        if (lane == 31) wsum[w] = incl;
        __syncthreads();
        if (w == 0) {
            int s = wsum[lane];
#pragma unroll
            for (int o = 1; o < 32; o <<= 1) {
                int u = __shfl_up_sync(0xffffffffu, s, o);
                if (lane >= o) s += u;
            }
            wsum[lane] = s;
        }
        __syncthreads();
        incl += ((w > 0) ? wsum[w - 1] : 0) + s_boff;
        if (tid < CHUNK && i0 < N_NODES) {
            g_off[i0 + 1] = incl;
            g_cur[i0]     = incl - v;
        }
        if (blockIdx.x == 0 && tid == 0) g_off[0] = 0;
    }
    grid_barrier(4);

    // P4: scatter — 4 independent edges per iteration
    {
        int e = gtid;
        for (; e + 3 * NT < N_EDGES; e += 4 * NT) {
            int d0 = edge_dst(ei, e,          is64);
            int d1 = edge_dst(ei, e + NT,     is64);
            int d2 = edge_dst(ei, e + 2 * NT, is64);
            int d3 = edge_dst(ei, e + 3 * NT, is64);
            int s0 = edge_src(ei, e,          is64);
            int s1 = edge_src(ei, e + NT,     is64);
            int s2 = edge_src(ei, e + 2 * NT, is64);
            int s3 = edge_src(ei, e + 3 * NT, is64);
            int p0 = atomicAdd(&g_cur[d0], 1);
            int p1 = atomicAdd(&g_cur[d1], 1);
            int p2 = atomicAdd(&g_cur[d2], 1);
            int p3 = atomicAdd(&g_cur[d3], 1);
            g_csr[p0] = s0;
            g_csr[p1] = s1;
            g_csr[p2] = s2;
            g_csr[p3] = s3;
        }
        for (; e < N_EDGES; e += NT) {
            int d = edge_dst(ei, e, is64);
            int s = edge_src(ei, e, is64);
            int p = atomicAdd(&g_cur[d], 1);
            g_csr[p] = s;
        }
    }

    __syncthreads();
    if (tid == 0) {
        __threadfence();
        int d = atomicAdd(&g_done_ctr, 1);
        if (d == NBLK - 1) {
            g_barrier_ctr = 0;
            g_done_ctr = 0;
            __threadfence();
        }
    }
}

// ---------------- MMA helper ----------------
__device__ __forceinline__ void mma16_f16(float c[4],
                                          uint32_t a0, uint32_t a1, uint32_t a2, uint32_t a3,
                                          uint32_t b0, uint32_t b1) {
    asm volatile(
        "mma.sync.aligned.m16n8k16.row.col.f32.f16.f16.f32 "
        "{%0,%1,%2,%3}, {%4,%5,%6,%7}, {%8,%9}, {%0,%1,%2,%3};"
        : "+f"(c[0]), "+f"(c[1]), "+f"(c[2]), "+f"(c[3])
        : "r"(a0), "r"(a1), "r"(a2), "r"(a3), "r"(b0), "r"(b1));
}

__device__ __forceinline__ void split_h2(float2 f, uint32_t& hi, uint32_t& lo) {
    __half2 h = __floats2half2_rn(f.x, f.y);
    float l0 = f.x - __low2float(h);
    float l1 = f.y - __high2float(h);
    __half2 l = __floats2half2_rn(l0, l1);
    hi = *reinterpret_cast<uint32_t*>(&h);
    lo = *reinterpret_cast<uint32_t*>(&l);
}

// ---------------- GEMM1: fp16 MMA, A=x (fp32->hi/lo), B=W1 (hi/lo), 3 passes ----------------
template <int K, int N>
__global__ void __launch_bounds__(192, 2) mma_gemm_h1_kernel(
        const float* __restrict__ X, const float* __restrict__ W,
        __half* __restrict__ Y) {
    constexpr int NT  = N / 8;
    constexpr int KP  = K / 2;
    constexpr int PAD = (8 - (N % 32) + 32) % 32;
    constexpr int PS  = N + PAD;
    extern __shared__ uint32_t smem[];
    uint32_t* sHi = smem;
    uint32_t* sLo = smem + KP * PS;

    gdc_launch();

    int tid = threadIdx.x;
    for (int i = tid; i < KP * N; i += 192) {
        int kp = i / N, n = i % N;
        float2 wp = make_float2(__ldg(W + (2 * kp) * N + n), __ldg(W + (2 * kp + 1) * N + n));
        uint32_t hi, lo;
        split_h2(wp, hi, lo);
        sHi[kp * PS + n] = hi;
        sLo[kp * PS + n] = lo;
    }
    __syncthreads();

    int warp = tid >> 5, lane = tid & 31;
    int tig = lane & 3, grp = lane >> 2;
    int row0 = blockIdx.x * 192 + warp * 32;
    int r0 = row0 + grp,      r1 = row0 + grp + 8;
    int r2 = row0 + grp + 16, r3 = row0 + grp + 24;
    const float* xr0 = X + (size_t)((r0 < N_NODES) ? r0 : (N_NODES - 1)) * K;
    const float* xr1 = X + (size_t)((r1 < N_NODES) ? r1 : (N_NODES - 1)) * K;
    const float* xr2 = X + (size_t)((r2 < N_NODES) ? r2 : (N_NODES - 1)) * K;
    const float* xr3 = X + (size_t)((r3 < N_NODES) ? r3 : (N_NODES - 1)) * K;

    float c0[NT][4], c1[NT][4];
#pragma unroll
    for (int nt = 0; nt < NT; nt++)
#pragma unroll
        for (int j = 0; j < 4; j++) { c0[nt][j] = 0.f; c1[nt][j] = 0.f; }

#pragma unroll 1
    for (int k0 = 0; k0 < K; k0 += 16) {
        float2 f00 = *(const float2*)(xr0 + k0 + 2 * tig);
        float2 f01 = *(const float2*)(xr1 + k0 + 2 * tig);
        float2 f02 = *(const float2*)(xr0 + k0 + 2 * tig + 8);
        float2 f03 = *(const float2*)(xr1 + k0 + 2 * tig + 8);
        float2 f10 = *(const float2*)(xr2 + k0 + 2 * tig);
        float2 f11 = *(const float2*)(xr3 + k0 + 2 * tig);
        float2 f12 = *(const float2*)(xr2 + k0 + 2 * tig + 8);
        float2 f13 = *(const float2*)(xr3 + k0 + 2 * tig + 8);
        uint32_t ah0[4], al0[4], ah1[4], al1[4];
        split_h2(f00, ah0[0], al0[0]); split_h2(f01, ah0[1], al0[1]);
        split_h2(f02, ah0[2], al0[2]); split_h2(f03, ah0[3], al0[3]);
        split_h2(f10, ah1[0], al1[0]); split_h2(f11, ah1[1], al1[1]);
        split_h2(f12, ah1[2], al1[2]); split_h2(f13, ah1[3], al1[3]);

        int kp0 = (k0 >> 1) + tig;
        int kp1 = kp0 + 4;
        const uint32_t* rHi0 = sHi + kp0 * PS + grp;
        const uint32_t* rHi1 = sHi + kp1 * PS + grp;
        const uint32_t* rLo0 = sLo + kp0 * PS + grp;
        const uint32_t* rLo1 = sLo + kp1 * PS + grp;
#pragma unroll
        for (int nt = 0; nt < NT; nt++) {
            uint32_t b0h = rHi0[nt * 8], b1h = rHi1[nt * 8];
            uint32_t b0l = rLo0[nt * 8], b1l = rLo1[nt * 8];
            mma16_f16(c0[nt], ah0[0], ah0[1], ah0[2], ah0[3], b0h, b1h);
            mma16_f16(c0[nt], al0[0], al0[1], al0[2], al0[3], b0h, b1h);
            mma16_f16(c0[nt], ah0[0], ah0[1], ah0[2], ah0[3], b0l, b1l);
            mma16_f16(c1[nt], ah1[0], ah1[1], ah1[2], ah1[3], b0h, b1h);
            mma16_f16(c1[nt], al1[0], al1[1], al1[2], al1[3], b0h, b1h);
            mma16_f16(c1[nt], ah1[0], ah1[1], ah1[2], ah1[3], b0l, b1l);
        }
    }

#pragma unroll
    for (int nt = 0; nt < NT; nt++) {
        int col = nt * 8 + 2 * tig;
        if (r0 < N_NODES)
            *(__half2*)(Y + (size_t)r0 * N + col) = __floats2half2_rn(c0[nt][0], c0[nt][1]);
        if (r1 < N_NODES)
            *(__half2*)(Y + (size_t)r1 * N + col) = __floats2half2_rn(c0[nt][2], c0[nt][3]);
        if (r2 < N_NODES)
            *(__half2*)(Y + (size_t)r2 * N + col) = __floats2half2_rn(c1[nt][0], c1[nt][1]);
        if (r3 < N_NODES)
            *(__half2*)(Y + (size_t)r3 * N + col) = __floats2half2_rn(c1[nt][2], c1[nt][3]);
    }
}

// ---------------- GEMM2/3: fp16 m16n8k16, A fp16 direct, W = hi+lo (2 passes), PDL ----------------
template <int K, int N>
__global__ void __launch_bounds__(192, 2) mma_gemm_h_kernel(
        const __half* __restrict__ X, const float* __restrict__ W,
        __half* __restrict__ Y) {
    constexpr int NT  = N / 8;
    constexpr int KP  = K / 2;
    constexpr int PAD = (8 - (N % 32) + 32) % 32;
    constexpr int PS  = N + PAD;
    extern __shared__ uint32_t smem[];
    uint32_t* sHi = smem;
    uint32_t* sLo = smem + KP * PS;

    gdc_launch();

    // prologue: stage W (kernel input, independent of predecessor output)
    int tid = threadIdx.x;
    for (int i = tid; i < KP * N; i += 192) {
        int kp = i / N, n = i % N;
        float2 wp = make_float2(__ldg(W + (2 * kp) * N + n), __ldg(W + (2 * kp + 1) * N + n));
        uint32_t hi, lo;
        split_h2(wp, hi, lo);
        sHi[kp * PS + n] = hi;
        sLo[kp * PS + n] = lo;
    }
    __syncthreads();

    int warp = tid >> 5, lane = tid & 31;
    int tig = lane & 3, grp = lane >> 2;
    int row0 = blockIdx.x * 192 + warp * 32;
    int r0 = row0 + grp,      r1 = row0 + grp + 8;
    int r2 = row0 + grp + 16, r3 = row0 + grp + 24;
    const __half* xr0 = X + (size_t)((r0 < N_NODES) ? r0 : (N_NODES - 1)) * K;
    const __half* xr1 = X + (size_t)((r1 < N_NODES) ? r1 : (N_NODES - 1)) * K;
    const __half* xr2 = X + (size_t)((r2 < N_NODES) ? r2 : (N_NODES - 1)) * K;
    const __half* xr3 = X + (size_t)((r3 < N_NODES) ? r3 : (N_NODES - 1)) * K;

    float c0[NT][4], c1[NT][4];
#pragma unroll
    for (int nt = 0; nt < NT; nt++)
#pragma unroll
        for (int j = 0; j < 4; j++) { c0[nt][j] = 0.f; c1[nt][j] = 0.f; }

    gdc_wait();   // predecessor (agg) output X becomes valid here

#pragma unroll 1
    for (int k0 = 0; k0 < K; k0 += 16) {
        uint32_t a00 = __ldg((const uint32_t*)(xr0 + k0 + 2 * tig));
        uint32_t a01 = __ldg((const uint32_t*)(xr1 + k0 + 2 * tig));
        uint32_t a02 = __ldg((const uint32_t*)(xr0 + k0 + 2 * tig + 8));
        uint32_t a03 = __ldg((const uint32_t*)(xr1 + k0 + 2 * tig + 8));
        uint32_t a10 = __ldg((const uint32_t*)(xr2 + k0 + 2 * tig));
        uint32_t a11 = __ldg((const uint32_t*)(xr3 + k0 + 2 * tig));
        uint32_t a12 = __ldg((const uint32_t*)(xr2 + k0 + 2 * tig + 8));
        uint32_t a13 = __ldg((const uint32_t*)(xr3 + k0 + 2 * tig + 8));

        int kp0 = (k0 >> 1) + tig;
        int kp1 = kp0 + 4;
        const uint32_t* rHi0 = sHi + kp0 * PS + grp;
        const uint32_t* rHi1 = sHi + kp1 * PS + grp;
        const uint32_t* rLo0 = sLo + kp0 * PS + grp;
        const uint32_t* rLo1 = sLo + kp1 * PS + grp;
#pragma unroll
        for (int nt = 0; nt < NT; nt++) {
            uint32_t b0h = rHi0[nt * 8], b1h = rHi1[nt * 8];
            uint32_t b0l = rLo0[nt * 8], b1l = rLo1[nt * 8];
            mma16_f16(c0[nt], a00, a01, a02, a03, b0h, b1h);
            mma16_f16(c0[nt], a00, a01, a02, a03, b0l, b1l);
            mma16_f16(c1[nt], a10, a11, a12, a13, b0h, b1h);
            mma16_f16(c1[nt], a10, a11, a12, a13, b0l, b1l);
        }
    }

#pragma unroll
    for (int nt = 0; nt < NT; nt++) {
        int col = nt * 8 + 2 * tig;
        if (r0 < N_NODES)
            *(__half2*)(Y + (size_t)r0 * N + col) = __floats2half2_rn(c0[nt][0], c0[nt][1]);
        if (r1 < N_NODES)
            *(__half2*)(Y + (size_t)r1 * N + col) = __floats2half2_rn(c0[nt][2], c0[nt][3]);
        if (r2 < N_NODES)
            *(__half2*)(Y + (size_t)r2 * N + col) = __floats2half2_rn(c1[nt][0], c1[nt][1]);
        if (r3 < N_NODES)
            *(__half2*)(Y + (size_t)r3 * N + col) = __floats2half2_rn(c1[nt][2], c1[nt][3]);
    }
}

// ---------------- gather aggregation (fp16 in, fp32 accum) + fused epilogue, PDL ----------------
__device__ __forceinline__ void acc_h4(float4& acc, uint2 v) {
    float2 f0 = __half22float2(*reinterpret_cast<__half2*>(&v.x));
    float2 f1 = __half22float2(*reinterpret_cast<__half2*>(&v.y));
    acc.x += f0.x; acc.y += f0.y; acc.z += f1.x; acc.w += f1.y;
}

// EPI 0: relu(acc+bias) -> fp16   EPI 1: log_softmax(acc+bias) -> fp32
template <int D, int EPI>
__global__ void agg_kernel(const __half* __restrict__ xin, const float* __restrict__ bias,
                           void* __restrict__ xout) {
    gdc_launch();
    int gw   = (blockIdx.x * blockDim.x + threadIdx.x) >> 5;
    int lane = threadIdx.x & 31;
    if (gw >= N_NODES) { gdc_wait(); return; }
    constexpr int D4 = D / 4;
    float4 acc = make_float4(0.f, 0.f, 0.f, 0.f);
    // prologue: CSR offsets + bias (independent of same-stream predecessor output)
    int beg = g_off[gw], end = g_off[gw + 1];
    float4 bb = (lane < D4) ? ((const float4*)bias)[lane] : make_float4(0.f, 0.f, 0.f, 0.f);

    gdc_wait();   // predecessor (gemm) output xin becomes valid here

    int e = beg;
    for (; e + 3 < end; e += 4) {
        int s0 = g_csr[e], s1 = g_csr[e + 1], s2 = g_csr[e + 2], s3 = g_csr[e + 3];
        if (lane < D4) {
            uint2 v0 = __ldg((const uint2*)(xin + (size_t)s0 * D) + lane);
            uint2 v1 = __ldg((const uint2*)(xin + (size_t)s1 * D) + lane);
            uint2 v2 = __ldg((const uint2*)(xin + (size_t)s2 * D) + lane);
            uint2 v3 = __ldg((const uint2*)(xin + (size_t)s3 * D) + lane);
            acc_h4(acc, v0);
            acc_h4(acc, v1);
            acc_h4(acc, v2);
            acc_h4(acc, v3);
        }
    }
    for (; e < end; e++) {
        int s0 = g_csr[e];
        if (lane < D4) {
            uint2 v = __ldg((const uint2*)(xin + (size_t)s0 * D) + lane);
            acc_h4(acc, v);
        }
    }
    acc.x += bb.x; acc.y += bb.y; acc.z += bb.z; acc.w += bb.w;

    if (EPI == 0) {
        if (lane < D4) {
            __half2 o0 = __floats2half2_rn(fmaxf(acc.x, 0.f), fmaxf(acc.y, 0.f));
            __half2 o1 = __floats2half2_rn(fmaxf(acc.z, 0.f), fmaxf(acc.w, 0.f));
            uint2 pack;
            pack.x = *reinterpret_cast<uint32_t*>(&o0);
            pack.y = *reinterpret_cast<uint32_t*>(&o1);
            ((uint2*)((__half*)xout + (size_t)gw * D))[lane] = pack;
        }
    } else {
        float m = (lane < D4)
                ? fmaxf(fmaxf(acc.x, acc.y), fmaxf(acc.z, acc.w))
                : -INFINITY;
#pragma unroll
        for (int o = 16; o > 0; o >>= 1) m = fmaxf(m, __shfl_xor_sync(0xffffffffu, m, o));
        float s = (lane < D4)
                ? (expf(acc.x - m) + expf(acc.y - m)) + (expf(acc.z - m) + expf(acc.w - m))
                : 0.f;
#pragma unroll
        for (int o = 16; o > 0; o >>= 1) s += __shfl_xor_sync(0xffffffffu, s, o);
        float l = m + logf(s);
        if (lane < D4) {
            acc.x -= l; acc.y -= l; acc.z -= l; acc.w -= l;
            ((float4*)((float*)xout + (size_t)gw * D))[lane] = acc;
        }
    }
}

// ---------------- launch ----------------
extern "C" void kernel_launch(void* const* d_in, const int* in_sizes, int n_in,
                              void* d_out, int out_size) {
    const float* x  = (const float*)d_in[0];
    const float* W1 = (const float*)d_in[1];
    const float* b1 = (const float*)d_in[2];
    const float* W2 = (const float*)d_in[3];
    const float* b2 = (const float*)d_in[4];
    const float* W3 = (const float*)d_in[5];
    const float* b3 = (const float*)d_in[6];
    const int*   ei = (const int*)d_in[7];
    float* out = (float*)d_out;

    __half *p_t1, *p_h1, *p_t2, *p_h2, *p_t3;
    cudaGetSymbolAddress((void**)&p_t1, g_t1);
    cudaGetSymbolAddress((void**)&p_h1, g_h1);
    cudaGetSymbolAddress((void**)&p_t2, g_t2);
    cudaGetSymbolAddress((void**)&p_h2, g_h2);
    cudaGetSymbolAddress((void**)&p_t3, g_t3);

    constexpr int PS1 = F1 + ((8 - (F1 % 32) + 32) % 32);   // 104
    constexpr int PS2 = F2 + ((8 - (F2 % 32) + 32) % 32);   // 104
    constexpr int PS3 = F3 + ((8 - (F3 % 32) + 32) % 32);   // 40
    const int smem1 = 2 * (F0 / 2) * PS1 * 4;
    const int smem2 = 2 * (F1 / 2) * PS2 * 4;
    const int smem3 = 2 * (F2 / 2) * PS3 * 4;

    static cudaStream_t sB = nullptr;
    static cudaEvent_t ev_fork = nullptr, ev_join = nullptr;
    if (!sB) {
        cudaStreamCreateWithFlags(&sB, cudaStreamNonBlocking);
        cudaEventCreateWithFlags(&ev_fork, cudaEventDisableTiming);
        cudaEventCreateWithFlags(&ev_join, cudaEventDisableTiming);
        cudaFuncSetAttribute(mma_gemm_h1_kernel<F0, F1>,
                             cudaFuncAttributeMaxDynamicSharedMemorySize, smem1);
        cudaFuncSetAttribute(mma_gemm_h_kernel<F1, F2>,
                             cudaFuncAttributeMaxDynamicSharedMemorySize, smem2);
        cudaFuncSetAttribute(mma_gemm_h_kernel<F2, F3>,
                             cudaFuncAttributeMaxDynamicSharedMemorySize, smem3);
    }

    // fork: persistent CSR build on sB, GEMM1 on main stream
    cudaEventRecord(ev_fork, 0);
    cudaStreamWaitEvent(sB, ev_fork, 0);
    csr_build_kernel<<<NBLK, CSR_THREADS, 0, sB>>>(ei);
    cudaEventRecord(ev_join, sB);

    const int agg_grid  = (N_NODES * 32 + 255) / 256;
    const int gemm_grid = (N_NODES + 191) / 192;

    // main stream: t1 = x @ W1
    mma_gemm_h1_kernel<F0, F1><<<gemm_grid, 192, smem1>>>(x, W1, p_t1);

    // join: aggregation needs CSR
    cudaStreamWaitEvent(0, ev_join, 0);

    // PDL-enabled launches for the post-fork chain
    cudaLaunchAttribute pdl[1];
    pdl[0].id = cudaLaunchAttributeProgrammaticStreamSerialization;
    pdl[0].val.programmaticStreamSerializationAllowed = 1;

    auto launch_agg = [&](auto kern, int grid, const __half* xin, const float* b, void* xo) {
        cudaLaunchConfig_t cfg = {};
        cfg.gridDim = dim3(grid);
        cfg.blockDim = dim3(256);
        cfg.dynamicSmemBytes = 0;
        cfg.stream = 0;
        cfg.attrs = pdl;
        cfg.numAttrs = 1;
        cudaLaunchKernelEx(&cfg, kern, xin, b, xo);
    };
    auto launch_gemm = [&](auto kern, int smem, const __half* X, const float* W, __half* Y) {
        cudaLaunchConfig_t cfg = {};
        cfg.gridDim = dim3(gemm_grid);
        cfg.blockDim = dim3(192);
        cfg.dynamicSmemBytes = (size_t)smem;
        cfg.stream = 0;
        cfg.attrs = pdl;
        cfg.numAttrs = 1;
        cudaLaunchKernelEx(&cfg, kern, X, W, Y);
    };

    // layer 1: h1 = relu(agg(t1) + b1)
    launch_agg(agg_kernel<F1, 0>, agg_grid, p_t1, b1, (void*)p_h1);
    // layer 2
    launch_gemm(mma_gemm_h_kernel<F1, F2>, smem2, p_h1, W2, p_t2);
    launch_agg(agg_kernel<F2, 0>, agg_grid, p_t2, b2, (void*)p_h2);
    // layer 3 + log_softmax
    launch_gemm(mma_gemm_h_kernel<F2, F3>, smem3, p_h2, W3, p_t3);
    launch_agg(agg_kernel<F3, 1>, agg_grid, p_t3, b3, (void*)out);
}